// round 14
// baseline (speedup 1.0000x reference)
#include <cuda_runtime.h>
#include <cuda_bf16.h>
#include <cstdint>

// KOrderGPMap: B=32, L=64, C=4. x one-hot => s_l = 4*l + idx[b,l].
// phi[b] = th0 + sum th1[s_l] + sum_{l0<l1} th2[s0*256+s1]
//        + sum_{l0<l1<l2} th3[(s0<<16)+(s1<<8)+s2].
//
// One block per PAIR (l0,l1). The 16 (c0,c1) theta3 suffix rows are fetched
// with cp.async.bulk (1 instruction per row, mbarrier completion) -> LSU
// issue cost collapses vs per-lane LDG streaming. All 32 batches then gather
// from smem. Last-finishing block copies the spread scratch to out.

#define B 32
#define L 64
#define NT 128
#define NPAIRS 2016
#define PITCH 260   // floats per smem row; 260*4=1040 B, 16B-aligned rows

__device__ unsigned char d_c[B * L];      // transposed: d_c[l*32 + b]
__device__ float d_scratch[B * 64];       // batch b at [b*64] (256B stride)
__device__ int d_count;

// ---- prep: zero scratch/count + decode one-hot -> c table (8 blocks) ----
__global__ __launch_bounds__(256)
void prep_kernel(const float* __restrict__ x) {
    const int i = blockIdx.x * 256 + threadIdx.x;   // i = b*64 + l, [0,2048)
    if (blockIdx.x == 0) {
        if (threadIdx.x < B) d_scratch[threadIdx.x * 64] = 0.0f;
        if (threadIdx.x == 0) d_count = 0;
    }
    const float4 v = reinterpret_cast<const float4*>(x)[i];
    const unsigned char c =
        (unsigned char)(int)(v.y + 2.0f * v.z + 3.0f * v.w + 0.5f);
    d_c[(i & 63) * 32 + (i >> 6)] = c;              // [l*32 + b]
}

// ---- main ----
__global__ __launch_bounds__(NT)
void kgp8_kernel(const float* __restrict__ th0,
                 const float* __restrict__ th1,
                 const float* __restrict__ th2,
                 const float* __restrict__ th3,
                 float* __restrict__ out)
{
    __shared__ __align__(16) float suf[16 * PITCH]; // [c0*4+c1][4*(l2-l1-1)+c2]
    __shared__ unsigned char cs[B * L];             // cs[l*32+b]
    __shared__ float t2s[16];
    __shared__ float red[NT];
    __shared__ __align__(8) unsigned long long mbar;

    const int tid  = threadIdx.x;
    const int warp = tid >> 5;
    const int lane = tid & 31;

    // decode pair index -> (l0, l1), l0 < l1
    int p = blockIdx.x, l0 = 0;
    while (p >= 63 - l0) { p -= 63 - l0; ++l0; }
    const int l1 = l0 + 1 + p;
    const int w  = 63 - l1;                 // l2 values; row = w float4s

    uint32_t mbar_a;
    {
        uint64_t a64 = (uint64_t)__cvta_generic_to_shared(&mbar);
        mbar_a = (uint32_t)a64;
    }
    if (tid == 0) {
        asm volatile("mbarrier.init.shared.b64 [%0], %1;"
                     :: "r"(mbar_a), "r"(1) : "memory");
    }
    __syncthreads();

    // One bulk copy per (c0,c1) row; tid 0 programs the total tx bytes.
    const int row_bytes = 16 * w;
    if (tid == 0) {
        asm volatile("mbarrier.arrive.expect_tx.shared.b64 _, [%0], %1;"
                     :: "r"(mbar_a), "r"(16 * row_bytes) : "memory");
    }
    if (tid < 16 && w > 0) {
        const int c0 = tid >> 2, c1 = tid & 3;
        const float* src = th3 + (((4 * l0 + c0) << 16) +
                                  ((4 * l1 + c1) << 8) + 4 * (l1 + 1));
        uint32_t dst = (uint32_t)(uint64_t)__cvta_generic_to_shared(
                           &suf[tid * PITCH]);
        asm volatile(
            "cp.async.bulk.shared::cluster.global.mbarrier::complete_tx::bytes"
            " [%0], [%1], %2, [%3];"
            :: "r"(dst), "l"(src), "r"(row_bytes), "r"(mbar_a) : "memory");
    }

    // Overlap: c table (one int4 per thread) + theta2 combos.
    reinterpret_cast<int4*>(cs)[tid] = reinterpret_cast<const int4*>(d_c)[tid];
    if (tid < 16)
        t2s[tid] = __ldg(&th2[(4 * l0 + (tid >> 2)) * 256 + 4 * l1 + (tid & 3)]);

    // Wait for all 16 rows (acquire orders the async writes before our LDS).
    {
        uint32_t done;
        asm volatile(
            "{\n\t.reg .pred p;\n\t"
            "mbarrier.try_wait.parity.acquire.cta.shared::cta.b64 p, [%1], %2;\n\t"
            "selp.b32 %0, 1, 0, p;\n\t}"
            : "=r"(done) : "r"(mbar_a), "r"(0) : "memory");
        if (!done) {
            asm volatile(
                "{\n\t.reg .pred P1;\n\t"
                "WAIT_LOOP_%=:\n\t"
                "mbarrier.try_wait.parity.acquire.cta.shared::cta.b64 P1, [%0], %1, 0x989680;\n\t"
                "@P1 bra.uni WAIT_DONE_%=;\n\t"
                "bra.uni WAIT_LOOP_%=;\n\t"
                "WAIT_DONE_%=:\n\t}"
                :: "r"(mbar_a), "r"(0) : "memory");
        }
    }
    __syncthreads();   // cs/t2s visible to all; suf complete everywhere

    // compute: warp g, lane b (= batch). Thread sums l2 = l1+1+g step 4.
    const int b  = lane;
    const int cc = cs[l0 * 32 + b] * 4 + cs[l1 * 32 + b];
    const float* __restrict__ sufb = &suf[cc * PITCH];

    float acc = (warp == 0) ? t2s[cc] : 0.0f;   // order-2, once per batch
    #pragma unroll 4
    for (int l2 = l1 + 1 + warp; l2 < L; l2 += 4)
        acc += sufb[4 * (l2 - l1 - 1) + cs[l2 * 32 + b]];

    // order-1 + theta0 on the empty pair (62,63): warps 1,2, lane = batch.
    if (blockIdx.x == NPAIRS - 1 && (warp == 1 || warp == 2)) {
        const int lbase = (warp - 1) * 32;
        #pragma unroll
        for (int l = lbase; l < lbase + 32; ++l)
            acc += __ldg(&th1[4 * l + cs[l * 32 + b]]);
        if (warp == 1) acc += th0[0];
    }

    red[warp * 32 + b] = acc;
    __syncthreads();

    if (warp == 0) {
        const float tot = red[b] + red[32 + b] + red[64 + b] + red[96 + b];
        atomicAdd(&d_scratch[b * 64], tot);     // 256B stride: slice-parallel
        __threadfence();
        // ticket: last-finishing block writes the output (no final kernel).
        int last = 0;
        if (lane == 0) last = (atomicAdd(&d_count, 1) == NPAIRS - 1) ? 1 : 0;
        last = __shfl_sync(0xffffffffu, last, 0);
        if (last) {
            __threadfence();
            out[b] = d_scratch[b * 64];
        }
    }
}

extern "C" void kernel_launch(void* const* d_in, const int* in_sizes, int n_in,
                              void* d_out, int out_size) {
    const float* x   = (const float*)d_in[0];
    const float* th0 = (const float*)d_in[1];
    const float* th1 = (const float*)d_in[2];
    const float* th2 = (const float*)d_in[3];
    const float* th3 = (const float*)d_in[4];
    float* out = (float*)d_out;

    prep_kernel<<<8, 256>>>(x);
    kgp8_kernel<<<NPAIRS, NT>>>(th0, th1, th2, th3, out);
}